// round 2
// baseline (speedup 1.0000x reference)
#include <cuda_runtime.h>

// SingleChannelInterpolation — fully fused, two-pass streaming softmax in log2 domain.
// B=32, C=128, W=128, H=128, KAPPA=10.
// Outputs concatenated: y [B,C,H] | w [B,C,H] | y_trans [B,C,H].

constexpr int B = 32, C = 128, W = 128, H = 128;
constexpr int BDIM = 128;          // 4 warps per block
constexpr int CH_PER_BLOCK = 4;    // one warp per (b,c) channel
constexpr float LOG2E = 1.4426950408889634f;
constexpr float LN2   = 0.6931471805599453f;

__device__ __forceinline__ float ex2(float x) {
    float y; asm("ex2.approx.ftz.f32 %0, %1;" : "=f"(y) : "f"(x)); return y;
}
__device__ __forceinline__ float lg2(float x) {
    float y; asm("lg2.approx.ftz.f32 %0, %1;" : "=f"(y) : "f"(x)); return y;
}

__global__ __launch_bounds__(BDIM)
void interp_kernel(const float* __restrict__ x_t,
                   const float* __restrict__ d_in_,
                   const float* __restrict__ m_in,
                   const float* __restrict__ kern,
                   float* __restrict__ out)
{
    __shared__ float alpha2[W];                // softplus(kernel) * log2(e)
    __shared__ float4 P[CH_PER_BLOCK][W];      // (d, alpha2, log2(m), x)

    const int tid = threadIdx.x;

    // alpha = softplus(kernel), accurate path (setup only, amortized)
    if (tid < W) {
        float k = kern[tid];
        alpha2[tid] = log1pf(expf(k)) * LOG2E;
    }
    __syncthreads();

    const int bc0 = blockIdx.x * CH_PER_BLOCK;

    // Fill per-channel packed data: one float4 LDS covers the whole inner loop body.
    #pragma unroll
    for (int ch = 0; ch < CH_PER_BLOCK; ch++) {
        int g = (bc0 + ch) * W + tid;
        float dv = d_in_[g];
        float mv = m_in[g];
        float xv = x_t[g];
        P[ch][tid] = make_float4(dv, alpha2[tid], lg2(mv), xv);
    }
    __syncthreads();

    const int warp = tid >> 5;
    const int lane = tid & 31;
    const float4* __restrict__ Pc = P[warp];

    // Each lane owns 4 h values: h = lane + 32*j.  t = h * H/(H-1) (linspace(0,H,H)).
    float t[4], M[4], Mt[4];
    #pragma unroll
    for (int j = 0; j < 4; j++) {
        int h = lane + 32 * j;
        t[j]  = (float)h * (128.0f / 127.0f);
        M[j]  = -1e30f;
        Mt[j] = -1e30f;
    }

    // ---- Pass 1: per-h maxima of s2 = log2m - a2*(d-t)^2 and s2t = log2m - 10*a2*(d-t)^2
    #pragma unroll 4
    for (int w = 0; w < W; w++) {
        float4 p = Pc[w];
        #pragma unroll
        for (int j = 0; j < 4; j++) {
            float diff = p.x - t[j];
            float u    = p.y * diff;
            float q    = u * diff;            // a2*(d-t)^2  (direct form: no cancellation)
            float s2   = p.z - q;
            float s2t  = fmaf(-10.0f, q, p.z);
            M[j]  = fmaxf(M[j],  s2);
            Mt[j] = fmaxf(Mt[j], s2t);
        }
    }

    // ---- Pass 2: softmax-weighted sums (both kernels) with exact per-h max shift
    float S[4]  = {0.f, 0.f, 0.f, 0.f}, Y[4]  = {0.f, 0.f, 0.f, 0.f};
    float St[4] = {0.f, 0.f, 0.f, 0.f}, Yt[4] = {0.f, 0.f, 0.f, 0.f};
    #pragma unroll 2
    for (int w = 0; w < W; w++) {
        float4 p = Pc[w];
        #pragma unroll
        for (int j = 0; j < 4; j++) {
            float diff = p.x - t[j];
            float u    = p.y * diff;
            float q    = u * diff;
            float s2   = p.z - q;
            float e    = ex2(s2 - M[j]);
            S[j] += e;
            Y[j]  = fmaf(e, p.w, Y[j]);
            float s2t = fmaf(-10.0f, q, p.z);
            float et  = ex2(s2t - Mt[j]);
            St[j] += et;
            Yt[j]  = fmaf(et, p.w, Yt[j]);
        }
    }

    // ---- Epilogue: y, logsumexp (natural log), y_trans
    const int bc = bc0 + warp;
    #pragma unroll
    for (int j = 0; j < 4; j++) {
        int h = lane + 32 * j;
        int o = bc * H + h;
        out[o]               = __fdividef(Y[j], S[j]);
        out[B*C*H + o]       = LN2 * (M[j] + lg2(S[j]));
        out[2*B*C*H + o]     = __fdividef(Yt[j], St[j]);
    }
}

extern "C" void kernel_launch(void* const* d_in, const int* in_sizes, int n_in,
                              void* d_out, int out_size)
{
    const float* x_t  = (const float*)d_in[0];
    const float* d    = (const float*)d_in[1];
    const float* m    = (const float*)d_in[2];
    const float* kern = (const float*)d_in[3];
    float* out = (float*)d_out;

    interp_kernel<<<(B * C) / CH_PER_BLOCK, BDIM>>>(x_t, d, m, kern, out);
}

// round 4
// speedup vs baseline: 2.1361x; 2.1361x over previous
#include <cuda_runtime.h>

// SingleChannelInterpolation — fused two-pass softmax, f32x2-packed over w-pairs.
// B=32, C=128, W=128, H=128, KAPPA=10.
// Outputs: y [B,C,H] | w [B,C,H] | y_trans [B,C,H] (concatenated).
//
// log2-domain: s2 = log2(m) - alpha2*(d-t)^2,  alpha2 = softplus(kernel)*log2(e)
// transient:   s2t = 10*s2 - 9*log2(m); shifted by Mt' = 10*M + 45 (provably
//              within +-45 of true max since log2(m) in [-9.97, 0]) -> no 2nd max pass.

constexpr int B = 32, C = 128, W = 128, H = 128;
constexpr int BDIM = 128;          // 4 warps
constexpr int CH_PER_BLOCK = 4;    // one warp per (b,c) channel
constexpr int W2 = W / 2;
constexpr float LOG2E = 1.4426950408889634f;
constexpr float LN2   = 0.6931471805599453f;

typedef unsigned long long u64;

__device__ __forceinline__ float ex2(float x) {
    float y; asm("ex2.approx.ftz.f32 %0, %1;" : "=f"(y) : "f"(x)); return y;
}
__device__ __forceinline__ float lg2(float x) {
    float y; asm("lg2.approx.ftz.f32 %0, %1;" : "=f"(y) : "f"(x)); return y;
}
__device__ __forceinline__ u64 pk(float lo, float hi) {
    u64 r; asm("mov.b64 %0, {%1, %2};" : "=l"(r) : "f"(lo), "f"(hi)); return r;
}
__device__ __forceinline__ void unpk(u64 v, float& lo, float& hi) {
    asm("mov.b64 {%0, %1}, %2;" : "=f"(lo), "=f"(hi) : "l"(v));
}
__device__ __forceinline__ u64 add2(u64 a, u64 b) {
    u64 r; asm("add.rn.f32x2 %0, %1, %2;" : "=l"(r) : "l"(a), "l"(b)); return r;
}
__device__ __forceinline__ u64 mul2(u64 a, u64 b) {
    u64 r; asm("mul.rn.f32x2 %0, %1, %2;" : "=l"(r) : "l"(a), "l"(b)); return r;
}
__device__ __forceinline__ u64 fma2(u64 a, u64 b, u64 c) {
    u64 r; asm("fma.rn.f32x2 %0, %1, %2, %3;" : "=l"(r) : "l"(a), "l"(b), "l"(c)); return r;
}

__global__ __launch_bounds__(BDIM)
void interp_kernel(const float* __restrict__ x_t,
                   const float* __restrict__ d_in_,
                   const float* __restrict__ m_in,
                   const float* __restrict__ kern,
                   float* __restrict__ out)
{
    // SoA float2 shared: w-pairs load as single 64-bit LDS into aligned reg pairs.
    __shared__ float2 NA[W2];                   // {-alpha2[2k], -alpha2[2k+1]} (channel-indep)
    __shared__ float2 DD[CH_PER_BLOCK][W2];     // d pairs
    __shared__ float2 LL[CH_PER_BLOCK][W2];     // log2(m) pairs
    __shared__ float2 XX[CH_PER_BLOCK][W2];     // x pairs

    const int tid = threadIdx.x;
    const int bc0 = blockIdx.x * CH_PER_BLOCK;

    // setup: negated alpha2 (accurate softplus; amortized)
    {
        float k = kern[tid];
        ((float*)NA)[tid] = -log1pf(expf(k)) * LOG2E;
    }
    #pragma unroll
    for (int ch = 0; ch < CH_PER_BLOCK; ch++) {
        int g = (bc0 + ch) * W + tid;
        ((float*)DD[ch])[tid] = d_in_[g];
        ((float*)LL[ch])[tid] = lg2(m_in[g]);
        ((float*)XX[ch])[tid] = x_t[g];
    }
    __syncthreads();

    const int warp = tid >> 5;
    const int lane = tid & 31;
    const u64* __restrict__ dd_s = (const u64*)DD[warp];
    const u64* __restrict__ na_s = (const u64*)NA;
    const u64* __restrict__ ll_s = (const u64*)LL[warp];
    const u64* __restrict__ xx_s = (const u64*)XX[warp];

    // per-lane h targets: h = lane + 32*j, t = h * 128/127 (linspace(0,128,128))
    u64 nt2[4];
    float M[4];
    #pragma unroll
    for (int j = 0; j < 4; j++) {
        float t = (float)(lane + 32 * j) * (128.0f / 127.0f);
        nt2[j] = pk(-t, -t);
        M[j] = -1e30f;
    }

    // ---- Pass 1: M[j] = max_w s2   (3 packed + 2 FMNMX per w-pair per j)
    #pragma unroll 4
    for (int k = 0; k < W2; k++) {
        u64 dd = dd_s[k];
        u64 na = na_s[k];
        u64 ll = ll_s[k];
        #pragma unroll
        for (int j = 0; j < 4; j++) {
            u64 diff = add2(dd, nt2[j]);
            u64 v    = mul2(diff, diff);
            u64 s2   = fma2(na, v, ll);     // log2m - a2*(d-t)^2
            float a, b; unpk(s2, a, b);
            M[j] = fmaxf(M[j], fmaxf(a, b));
        }
    }

    u64 nM2[4];
    #pragma unroll
    for (int j = 0; j < 4; j++) nM2[j] = pk(-M[j], -M[j]);

    const u64 ten2 = pk(10.0f, 10.0f);
    const u64 n9   = pk(-9.0f, -9.0f);
    const u64 n45  = pk(-45.0f, -45.0f);

    // ---- Pass 2: softmax-weighted sums for both kernels
    float S[4]  = {0.f,0.f,0.f,0.f}, Y[4]  = {0.f,0.f,0.f,0.f};
    float St[4] = {0.f,0.f,0.f,0.f}, Yt[4] = {0.f,0.f,0.f,0.f};
    #pragma unroll 2
    for (int k = 0; k < W2; k++) {
        u64 dd = dd_s[k];
        u64 na = na_s[k];
        u64 ll = ll_s[k];
        u64 xx = xx_s[k];
        u64 rr = fma2(n9, ll, n45);         // -9*log2m - 45 (per pair, amortized)
        float x0, x1; unpk(xx, x0, x1);
        #pragma unroll
        for (int j = 0; j < 4; j++) {
            u64 diff = add2(dd, nt2[j]);
            u64 v    = mul2(diff, diff);
            u64 s2   = fma2(na, v, ll);
            u64 sM   = add2(s2, nM2[j]);         // s2 - M
            u64 sMt  = fma2(ten2, sM, rr);       // s2t - (10M+45)
            float p0, p1; unpk(sM,  p0, p1);
            float q0, q1; unpk(sMt, q0, q1);
            float e0 = ex2(p0), e1 = ex2(p1);
            float f0 = ex2(q0), f1 = ex2(q1);
            S[j]  += e0;                 S[j]  += e1;
            Y[j]   = fmaf(e0, x0, Y[j]); Y[j]   = fmaf(e1, x1, Y[j]);
            St[j] += f0;                 St[j] += f1;
            Yt[j]  = fmaf(f0, x0, Yt[j]); Yt[j] = fmaf(f1, x1, Yt[j]);
        }
    }

    // ---- Epilogue
    const int bc = bc0 + warp;
    #pragma unroll
    for (int j = 0; j < 4; j++) {
        int h = lane + 32 * j;
        int o = bc * H + h;
        out[o]           = __fdividef(Y[j],  S[j]);
        out[B*C*H + o]   = LN2 * (M[j] + lg2(S[j]));
        out[2*B*C*H + o] = __fdividef(Yt[j], St[j]);
    }
}

extern "C" void kernel_launch(void* const* d_in, const int* in_sizes, int n_in,
                              void* d_out, int out_size)
{
    const float* x_t  = (const float*)d_in[0];
    const float* d    = (const float*)d_in[1];
    const float* m    = (const float*)d_in[2];
    const float* kern = (const float*)d_in[3];
    float* out = (float*)d_out;

    interp_kernel<<<(B * C) / CH_PER_BLOCK, BDIM>>>(x_t, d, m, kern, out);
}